// round 1
// baseline (speedup 1.0000x reference)
#include <cuda_runtime.h>
#include <cstdint>

#define HD 128          // hidden dim H
#define TILE_M 128      // edges per CTA
#define NTHREADS 256    // 8 warps
#define XS_STRIDE 260   // X smem row stride (floats), 260 % 32 == 4 -> conflict-free A frags
#define HS_STRIDE 132   // H / MSG smem row stride (floats)

// smem region size in floats: X uses 128*260; H+MSG reuse it as 2 * 128*132
#define SMEM_FLOATS (2 * TILE_M * HS_STRIDE > TILE_M * XS_STRIDE ? 2 * TILE_M * HS_STRIDE : TILE_M * XS_STRIDE)

__device__ __forceinline__ uint32_t f2tf(float f) {
    uint32_t u;
    asm("cvt.rna.tf32.f32 %0, %1;" : "=r"(u) : "f"(f));
    return u;
}

__device__ __forceinline__ void mma_tf32(float* c, const uint32_t* a, uint32_t b0, uint32_t b1) {
    asm volatile(
        "mma.sync.aligned.m16n8k8.row.col.f32.tf32.tf32.f32 "
        "{%0,%1,%2,%3}, {%4,%5,%6,%7}, {%8,%9}, {%0,%1,%2,%3};"
        : "+f"(c[0]), "+f"(c[1]), "+f"(c[2]), "+f"(c[3])
        : "r"(a[0]), "r"(a[1]), "r"(a[2]), "r"(a[3]), "r"(b0), "r"(b1));
}

__global__ void zero_kernel(float4* __restrict__ out, int n4) {
    int i = blockIdx.x * blockDim.x + threadIdx.x;
    if (i < n4) out[i] = make_float4(0.f, 0.f, 0.f, 0.f);
}

__global__ void __launch_bounds__(NTHREADS, 1)
relmp_kernel(const float* __restrict__ node_states,
             const int*   __restrict__ adj,
             const float* __restrict__ W1,
             const float* __restrict__ W2,
             float*       __restrict__ out,
             int E)
{
    extern __shared__ char smem_raw[];
    int*   s_src = (int*)smem_raw;
    int*   s_tgt = s_src + TILE_M;
    float* s_X   = (float*)(s_tgt + TILE_M);   // X tile; later reused as H then MSG

    const int t    = blockIdx.y;
    const int e0   = blockIdx.x * TILE_M;
    const int m_valid = min(TILE_M, E - e0);
    const int tid  = threadIdx.x;

    // ---- load edge indices ----
    if (tid < TILE_M) {
        int e = e0 + tid;
        int2 p = (e < E) ? ((const int2*)adj)[(size_t)t * E + e] : make_int2(0, 0);
        s_src[tid] = p.x;
        s_tgt[tid] = p.y;
    }
    __syncthreads();

    // ---- gather X = [src_state | tgt_state], convert to tf32, store to smem ----
    {
        const int rbase = tid >> 3;   // 8 threads per row, 32 rows in flight
        const int lane8 = tid & 7;
        for (int r = rbase; r < 2 * TILE_M; r += 32) {
            int m = r >> 1, side = r & 1;
            int node = side ? s_tgt[m] : s_src[m];
            const float4* srcp = (const float4*)(node_states + (size_t)node * HD);
            uint32_t* dst = (uint32_t*)(s_X + m * XS_STRIDE + side * HD);
            #pragma unroll
            for (int q = 0; q < 4; q++) {
                int f = lane8 + q * 8;            // float4 index 0..31
                float4 v = srcp[f];
                uint4 w;
                w.x = f2tf(v.x); w.y = f2tf(v.y); w.z = f2tf(v.z); w.w = f2tf(v.w);
                *(uint4*)(dst + f * 4) = w;
            }
        }
    }
    __syncthreads();

    const int lane = tid & 31, warp = tid >> 5;
    const int gid = lane >> 2, tig = lane & 3;
    const int wm = warp & 3, wn = warp >> 2;   // warp grid 4 (M) x 2 (N)

    // ================= GEMM1: H = relu(X @ W1), K = 256 =================
    const float* W1t = W1 + (size_t)t * (2 * HD * HD);
    float acc[2][8][4];
    #pragma unroll
    for (int i = 0; i < 2; i++)
        #pragma unroll
        for (int j = 0; j < 8; j++)
            #pragma unroll
            for (int q = 0; q < 4; q++) acc[i][j][q] = 0.f;

    {
        const uint32_t* Xs = (const uint32_t*)s_X;
        const int rA0 = wm * 32 + gid;
        const int cB  = wn * 64 + gid;
        #pragma unroll 4
        for (int k = 0; k < 2 * HD; k += 8) {
            uint32_t b[8][2];
            const float* w0 = W1t + (size_t)(k + tig) * HD;
            const float* w1 = w0 + 4 * HD;
            #pragma unroll
            for (int j = 0; j < 8; j++) {
                b[j][0] = f2tf(w0[cB + j * 8]);
                b[j][1] = f2tf(w1[cB + j * 8]);
            }
            uint32_t a[2][4];
            #pragma unroll
            for (int i = 0; i < 2; i++) {
                const uint32_t* xr0 = Xs + (rA0 + i * 16) * XS_STRIDE + k;
                const uint32_t* xr1 = xr0 + 8 * XS_STRIDE;
                a[i][0] = xr0[tig];
                a[i][1] = xr1[tig];
                a[i][2] = xr0[tig + 4];
                a[i][3] = xr1[tig + 4];
            }
            #pragma unroll
            for (int i = 0; i < 2; i++)
                #pragma unroll
                for (int j = 0; j < 8; j++)
                    mma_tf32(acc[i][j], a[i], b[j][0], b[j][1]);
        }
    }
    __syncthreads();   // X tile dead; reuse region for H

    // ---- store relu(H) as tf32 to smem ----
    {
        uint32_t* Hs = (uint32_t*)s_X;
        #pragma unroll
        for (int i = 0; i < 2; i++) {
            int row0 = wm * 32 + i * 16 + gid;
            #pragma unroll
            for (int j = 0; j < 8; j++) {
                int col = wn * 64 + j * 8 + tig * 2;
                uint2 lo, hi;
                lo.x = f2tf(fmaxf(acc[i][j][0], 0.f));
                lo.y = f2tf(fmaxf(acc[i][j][1], 0.f));
                hi.x = f2tf(fmaxf(acc[i][j][2], 0.f));
                hi.y = f2tf(fmaxf(acc[i][j][3], 0.f));
                *(uint2*)(Hs + row0 * HS_STRIDE + col)       = lo;
                *(uint2*)(Hs + (row0 + 8) * HS_STRIDE + col) = hi;
            }
        }
    }
    __syncthreads();

    // ================= GEMM2: MSG = relu(H @ W2), K = 128 =================
    const float* W2t = W2 + (size_t)t * (HD * HD);
    float acc2[2][8][4];
    #pragma unroll
    for (int i = 0; i < 2; i++)
        #pragma unroll
        for (int j = 0; j < 8; j++)
            #pragma unroll
            for (int q = 0; q < 4; q++) acc2[i][j][q] = 0.f;

    {
        const uint32_t* Hs = (const uint32_t*)s_X;
        const int rA0 = wm * 32 + gid;
        const int cB  = wn * 64 + gid;
        #pragma unroll 4
        for (int k = 0; k < HD; k += 8) {
            uint32_t b[8][2];
            const float* w0 = W2t + (size_t)(k + tig) * HD;
            const float* w1 = w0 + 4 * HD;
            #pragma unroll
            for (int j = 0; j < 8; j++) {
                b[j][0] = f2tf(w0[cB + j * 8]);
                b[j][1] = f2tf(w1[cB + j * 8]);
            }
            uint32_t a[2][4];
            #pragma unroll
            for (int i = 0; i < 2; i++) {
                const uint32_t* hr0 = Hs + (rA0 + i * 16) * HS_STRIDE + k;
                const uint32_t* hr1 = hr0 + 8 * HS_STRIDE;
                a[i][0] = hr0[tig];
                a[i][1] = hr1[tig];
                a[i][2] = hr0[tig + 4];
                a[i][3] = hr1[tig + 4];
            }
            #pragma unroll
            for (int i = 0; i < 2; i++)
                #pragma unroll
                for (int j = 0; j < 8; j++)
                    mma_tf32(acc2[i][j], a[i], b[j][0], b[j][1]);
        }
    }
    __syncthreads();   // H region now dead for writing MSG? (MSG uses disjoint half)

    // ---- store relu(MSG) fp32 to smem (second half of region) ----
    {
        float* Ms = s_X + TILE_M * HS_STRIDE;
        #pragma unroll
        for (int i = 0; i < 2; i++) {
            int row0 = wm * 32 + i * 16 + gid;
            #pragma unroll
            for (int j = 0; j < 8; j++) {
                int col = wn * 64 + j * 8 + tig * 2;
                float2 lo, hi;
                lo.x = fmaxf(acc2[i][j][0], 0.f);
                lo.y = fmaxf(acc2[i][j][1], 0.f);
                hi.x = fmaxf(acc2[i][j][2], 0.f);
                hi.y = fmaxf(acc2[i][j][3], 0.f);
                *(float2*)(Ms + row0 * HS_STRIDE + col)       = lo;
                *(float2*)(Ms + (row0 + 8) * HS_STRIDE + col) = hi;
            }
        }
    }
    __syncthreads();

    // ---- scatter-add: one warp per row, red.global.add.v4.f32 ----
    {
        const float* Ms = s_X + TILE_M * HS_STRIDE;
        const int rlane = tid & 31;
        for (int m = tid >> 5; m < m_valid; m += 8) {
            int node = s_tgt[m];
            float4 v = *(const float4*)(Ms + m * HS_STRIDE + rlane * 4);
            float* dst = out + (size_t)node * HD + rlane * 4;
            asm volatile("red.global.add.v4.f32 [%0], {%1,%2,%3,%4};"
                         :: "l"(dst), "f"(v.x), "f"(v.y), "f"(v.z), "f"(v.w)
                         : "memory");
        }
    }
}

extern "C" void kernel_launch(void* const* d_in, const int* in_sizes, int n_in,
                              void* d_out, int out_size)
{
    const float* node_states = (const float*)d_in[0];
    const int*   adj         = (const int*)d_in[1];
    const float* W1          = (const float*)d_in[2];
    const float* W2          = (const float*)d_in[3];
    float*       out         = (float*)d_out;

    // shapes: H fixed at 128; T from W2 = T*H*H; E from adj = T*E*2
    const int T = in_sizes[3] / (HD * HD);
    const int E = in_sizes[1] / (T * 2);

    // zero-init output (poisoned by harness)
    int n4 = out_size / 4;
    zero_kernel<<<(n4 + 255) / 256, 256>>>((float4*)out, n4);

    const int tiles = (E + TILE_M - 1) / TILE_M;
    const size_t smem = 2 * TILE_M * sizeof(int) + (size_t)SMEM_FLOATS * sizeof(float);
    cudaFuncSetAttribute(relmp_kernel, cudaFuncAttributeMaxDynamicSharedMemorySize, (int)smem);
    relmp_kernel<<<dim3(tiles, T), NTHREADS, smem>>>(node_states, adj, W1, W2, out, E);
}

// round 3
// speedup vs baseline: 2.0297x; 2.0297x over previous
#include <cuda_runtime.h>
#include <cstdint>

#define HD 128
#define TILE_M 128
#define NTH 256
#define MAXT 8
#define XSTR 132                    // X/H/MSG row stride (floats), 132%32==4 -> conflict-free LDSM
#define WSTR 36                     // W chunk row stride (floats), 36%32==4
#define WCH_B (128 * WSTR * 4)      // 18432 bytes per W chunk (128 n-rows x 32 k + pad)
#define X_BYTES (TILE_M * XSTR * 4) // 67584
#define X_OFF 0
#define W_OFF X_BYTES
#define IDX_OFF (W_OFF + 2 * WCH_B)       // 104448
#define MB_OFF (IDX_OFF + 2 * TILE_M * 4) // 105472
#define SMEM_DYN (MB_OFF + 32)

// pre-transposed tf32 weights: [t][chunk][n=128][WSTR], k-contiguous rows of n
__device__ __align__(16) float g_W1t[MAXT * 8 * 128 * WSTR];
__device__ __align__(16) float g_W2t[MAXT * 4 * 128 * WSTR];

static __device__ __forceinline__ uint32_t f2tf(float f) {
    uint32_t u; asm("cvt.rna.tf32.f32 %0, %1;" : "=r"(u) : "f"(f)); return u;
}
static __device__ __forceinline__ uint32_t s2u(const void* p) {
    uint32_t a;
    asm("{ .reg .u64 t; cvta.to.shared.u64 t, %1; cvt.u32.u64 %0, t; }" : "=r"(a) : "l"(p));
    return a;
}
static __device__ __forceinline__ void mma_tf32(float* c, const uint32_t* a, uint32_t b0, uint32_t b1) {
    asm volatile(
        "mma.sync.aligned.m16n8k8.row.col.f32.tf32.tf32.f32 "
        "{%0,%1,%2,%3}, {%4,%5,%6,%7}, {%8,%9}, {%0,%1,%2,%3};"
        : "+f"(c[0]), "+f"(c[1]), "+f"(c[2]), "+f"(c[3])
        : "r"(a[0]), "r"(a[1]), "r"(a[2]), "r"(a[3]), "r"(b0), "r"(b1));
}
static __device__ __forceinline__ void ldsm4(uint32_t* r, uint32_t addr) {
    asm volatile("ldmatrix.sync.aligned.m8n8.x4.shared.b16 {%0,%1,%2,%3}, [%4];"
                 : "=r"(r[0]), "=r"(r[1]), "=r"(r[2]), "=r"(r[3]) : "r"(addr));
}
static __device__ __forceinline__ void mbar_init(uint32_t m, uint32_t cnt) {
    asm volatile("mbarrier.init.shared.b64 [%0], %1;" :: "r"(m), "r"(cnt) : "memory");
}
static __device__ __forceinline__ void mbar_expect(uint32_t m, uint32_t bytes) {
    asm volatile("mbarrier.arrive.expect_tx.shared.b64 _, [%0], %1;" :: "r"(m), "r"(bytes) : "memory");
}
static __device__ __forceinline__ void mbar_arrive(uint32_t m) {
    asm volatile("mbarrier.arrive.shared.b64 _, [%0];" :: "r"(m) : "memory");
}
static __device__ __forceinline__ void mbar_wait(uint32_t m, uint32_t parity) {
    asm volatile(
        "{\n\t.reg .pred P;\n\tW_%=:\n\t"
        "mbarrier.try_wait.parity.shared.b64 P, [%0], %1;\n\t"
        "@!P bra W_%=;\n\t}"
        :: "r"(m), "r"(parity) : "memory");
}
static __device__ __forceinline__ void bulk_ld(uint32_t dst, const void* src, uint32_t bytes, uint32_t mbar) {
    asm volatile("cp.async.bulk.shared::cta.global.mbarrier::complete_tx::bytes [%0], [%1], %2, [%3];"
                 :: "r"(dst), "l"(src), "r"(bytes), "r"(mbar) : "memory");
}

// ---------------- prep: transpose + tf32-convert weights into chunked padded images ----------------
__global__ void prep_w(const float* __restrict__ W1, const float* __restrict__ W2, int T) {
    int idx = blockIdx.x * blockDim.x + threadIdx.x;
    const int per_t1 = 8 * 128 * 32, per_t2 = 4 * 128 * 32;
    int tot1 = T * per_t1, tot2 = T * per_t2;
    if (idx < tot1) {
        int t = idx / per_t1, r = idx % per_t1;
        int c = r / (128 * 32), q = r % (128 * 32);
        int n = q / 32, kl = q % 32;
        float v = W1[(size_t)t * 256 * 128 + (size_t)(c * 32 + kl) * 128 + n];
        g_W1t[(((size_t)t * 8 + c) * 128 + n) * WSTR + kl] = __uint_as_float(f2tf(v));
    } else if (idx < tot1 + tot2) {
        int j = idx - tot1;
        int t = j / per_t2, r = j % per_t2;
        int c = r / (128 * 32), q = r % (128 * 32);
        int n = q / 32, kl = q % 32;
        float v = W2[(size_t)t * 128 * 128 + (size_t)(c * 32 + kl) * 128 + n];
        g_W2t[(((size_t)t * 4 + c) * 128 + n) * WSTR + kl] = __uint_as_float(f2tf(v));
    }
}

__global__ void zero_kernel(float4* __restrict__ out, int n4) {
    int i = blockIdx.x * blockDim.x + threadIdx.x;
    if (i < n4) out[i] = make_float4(0.f, 0.f, 0.f, 0.f);
}

// gather 128 node rows (tf32) into X region, row stride XSTR
static __device__ __forceinline__ void gather_half(float* X, const int* __restrict__ list,
                                                   const float* __restrict__ ns, int tid) {
    int warp = tid >> 5, lane = tid & 31;
    #pragma unroll 4
    for (int m = warp; m < TILE_M; m += 8) {
        int node = list[m];
        float4 v = ((const float4*)(ns + (size_t)node * HD))[lane];
        uint4 w;
        w.x = f2tf(v.x); w.y = f2tf(v.y); w.z = f2tf(v.z); w.w = f2tf(v.w);
        *(uint4*)(X + m * XSTR + lane * 4) = w;
    }
}

// one 32-k chunk: 4 k-steps, A via 2 ldsm.x4, B via 4 ldsm.x4, 16 mma per k-step
static __device__ __forceinline__ void gemm_chunk(float acc[2][8][4],
                                                  uint32_t xa0, uint32_t xa1, uint32_t wb) {
    #pragma unroll
    for (int ks = 0; ks < 4; ks++) {
        uint32_t a0[4], a1[4], bf[4][4];
        ldsm4(a0, xa0 + ks * 32);
        ldsm4(a1, xa1 + ks * 32);
        #pragma unroll
        for (int p = 0; p < 4; p++) ldsm4(bf[p], wb + p * (16 * WSTR * 4) + ks * 32);
        #pragma unroll
        for (int j = 0; j < 8; j++) {
            mma_tf32(acc[0][j], a0, bf[j >> 1][(j & 1) * 2], bf[j >> 1][(j & 1) * 2 + 1]);
            mma_tf32(acc[1][j], a1, bf[j >> 1][(j & 1) * 2], bf[j >> 1][(j & 1) * 2 + 1]);
        }
    }
}

__global__ void __launch_bounds__(NTH, 2)
relmp_mma(const float* __restrict__ ns, const int* __restrict__ adj,
          float* __restrict__ out, int E) {
    extern __shared__ char raw[];
    float* X = (float*)(raw + X_OFF);
    uint32_t Su = s2u(raw);
    const uint32_t Xu = Su + X_OFF;
    const uint32_t Wu = Su + W_OFF;
    int* s_src = (int*)(raw + IDX_OFF);
    int* s_tgt = s_src + TILE_M;
    const uint32_t mbF[2] = { Su + MB_OFF, Su + MB_OFF + 8 };
    const uint32_t mbE[2] = { Su + MB_OFF + 16, Su + MB_OFF + 24 };

    const int tid = threadIdx.x, warp = tid >> 5, lane = tid & 31;
    const int gid = lane >> 2, tig = lane & 3;
    const int g = lane >> 3, gl = lane & 7;
    const int wm = warp & 3, wn = warp >> 2;
    const int t = blockIdx.y, e0 = blockIdx.x * TILE_M;
    const int m_valid = min(TILE_M, E - e0);

    if (tid == 0) {
        mbar_init(mbF[0], 1); mbar_init(mbF[1], 1);
        mbar_init(mbE[0], NTH); mbar_init(mbE[1], NTH);
    }
    if (tid < TILE_M) {
        int e = e0 + tid;
        int2 p = (e < E) ? ((const int2*)adj)[(size_t)t * E + e] : make_int2(0, 0);
        s_src[tid] = p.x; s_tgt[tid] = p.y;
    }
    __syncthreads();

    const float* w1b = g_W1t + (size_t)t * 8 * 128 * WSTR;
    const float* w2b = g_W2t + (size_t)t * 4 * 128 * WSTR;
    if (tid == 0) {
        mbar_expect(mbF[0], WCH_B); bulk_ld(Wu,         w1b,              WCH_B, mbF[0]);
        mbar_expect(mbF[1], WCH_B); bulk_ld(Wu + WCH_B, w1b + 128 * WSTR, WCH_B, mbF[1]);
    }

    // per-thread ldmatrix base offsets (bytes)
    const uint32_t arow0 = ((wm * 32 + gl + ((g & 1) << 3)) * XSTR + ((g >> 1) << 2)) * 4;
    const uint32_t arow1 = arow0 + 16 * XSTR * 4;
    const uint32_t brow  = ((wn * 64 + gl + ((g >> 1) << 3)) * WSTR + ((g & 1) << 2)) * 4;

    gather_half(X, s_src, ns, tid);
    __syncthreads();

    int pf[2] = {0, 0}, pe[2] = {0, 0};

#define CONSUME(cidx, ccolbytes, ACC) do {                                         \
        const int b_ = (cidx) & 1;                                                 \
        mbar_wait(mbF[b_], pf[b_]); pf[b_] ^= 1;                                   \
        gemm_chunk(ACC, Xu + arow0 + (ccolbytes), Xu + arow1 + (ccolbytes),        \
                   Wu + b_ * WCH_B + brow);                                        \
        mbar_arrive(mbE[b_]);                                                      \
        if (tid == 0 && (cidx) + 2 < 12) {                                         \
            mbar_wait(mbE[b_], pe[b_]); pe[b_] ^= 1;                               \
            const float* src_ = ((cidx) + 2 < 8) ? (w1b + ((cidx) + 2) * 128 * WSTR) \
                                                 : (w2b + ((cidx) - 6) * 128 * WSTR); \
            mbar_expect(mbF[b_], WCH_B);                                           \
            bulk_ld(Wu + b_ * WCH_B, src_, WCH_B, mbF[b_]);                        \
        }                                                                          \
    } while (0)

    float acc[2][8][4];
    #pragma unroll
    for (int i = 0; i < 2; i++)
        #pragma unroll
        for (int j = 0; j < 8; j++)
            #pragma unroll
            for (int q = 0; q < 4; q++) acc[i][j][q] = 0.f;

    // GEMM1 over src half (W1 chunks 0..3)
    #pragma unroll
    for (int c = 0; c < 4; c++) CONSUME(c, c * 128, acc);
    __syncthreads();

    gather_half(X, s_tgt, ns, tid);
    __syncthreads();

    // GEMM1 over tgt half (W1 chunks 4..7)
    #pragma unroll
    for (int c = 4; c < 8; c++) CONSUME(c, (c - 4) * 128, acc);
    __syncthreads();

    // epilogue1: H = relu(acc) -> tf32 into X region
    {
        uint32_t* Hs = (uint32_t*)X;
        #pragma unroll
        for (int i = 0; i < 2; i++) {
            int r0 = wm * 32 + i * 16 + gid;
            #pragma unroll
            for (int j = 0; j < 8; j++) {
                int cn = wn * 64 + j * 8 + tig * 2;
                uint2 lo, hi;
                lo.x = f2tf(fmaxf(acc[i][j][0], 0.f));
                lo.y = f2tf(fmaxf(acc[i][j][1], 0.f));
                hi.x = f2tf(fmaxf(acc[i][j][2], 0.f));
                hi.y = f2tf(fmaxf(acc[i][j][3], 0.f));
                *(uint2*)(Hs + r0 * XSTR + cn)       = lo;
                *(uint2*)(Hs + (r0 + 8) * XSTR + cn) = hi;
            }
        }
    }
    __syncthreads();

    // GEMM2: MSG = relu(H @ W2) (W2 chunks = global chunks 8..11)
    float acc2[2][8][4];
    #pragma unroll
    for (int i = 0; i < 2; i++)
        #pragma unroll
        for (int j = 0; j < 8; j++)
            #pragma unroll
            for (int q = 0; q < 4; q++) acc2[i][j][q] = 0.f;

    #pragma unroll
    for (int c = 8; c < 12; c++) CONSUME(c, (c - 8) * 128, acc2);
    __syncthreads();

    // epilogue2: relu(MSG) fp32 -> X region
    #pragma unroll
    for (int i = 0; i < 2; i++) {
        int r0 = wm * 32 + i * 16 + gid;
        #pragma unroll
        for (int j = 0; j < 8; j++) {
            int cn = wn * 64 + j * 8 + tig * 2;
            float2 lo, hi;
            lo.x = fmaxf(acc2[i][j][0], 0.f);
            lo.y = fmaxf(acc2[i][j][1], 0.f);
            hi.x = fmaxf(acc2[i][j][2], 0.f);
            hi.y = fmaxf(acc2[i][j][3], 0.f);
            *(float2*)(X + r0 * XSTR + cn)       = lo;
            *(float2*)(X + (r0 + 8) * XSTR + cn) = hi;
        }
    }
    __syncthreads();

    // scatter-add: warp per row, red.global.add.v4
    for (int m = warp; m < m_valid; m += 8) {
        int node = s_tgt[m];
        float4 v = *(const float4*)(X + m * XSTR + lane * 4);
        float* dst = out + (size_t)node * HD + lane * 4;
        asm volatile("red.global.add.v4.f32 [%0], {%1,%2,%3,%4};"
                     :: "l"(dst), "f"(v.x), "f"(v.y), "f"(v.z), "f"(v.w) : "memory");
    }
#undef CONSUME
}

extern "C" void kernel_launch(void* const* d_in, const int* in_sizes, int n_in,
                              void* d_out, int out_size) {
    const float* node_states = (const float*)d_in[0];
    const int*   adj         = (const int*)d_in[1];
    const float* W1          = (const float*)d_in[2];
    const float* W2          = (const float*)d_in[3];
    float*       out         = (float*)d_out;

    const int T = in_sizes[3] / (HD * HD);
    const int E = in_sizes[1] / (T * 2);

    int n4 = out_size / 4;
    zero_kernel<<<(n4 + 255) / 256, 256>>>((float4*)out, n4);

    int wtot = T * (8 + 4) * 128 * 32;
    prep_w<<<(wtot + 255) / 256, 256>>>(W1, W2, T);

    const int tiles = (E + TILE_M - 1) / TILE_M;
    cudaFuncSetAttribute(relmp_mma, cudaFuncAttributeMaxDynamicSharedMemorySize, SMEM_DYN);
    relmp_mma<<<dim3(tiles, T), NTH, SMEM_DYN>>>(node_states, adj, out, E);
}

// round 7
// speedup vs baseline: 2.7245x; 1.3423x over previous
#include <cuda_runtime.h>
#include <cuda_fp16.h>
#include <cstdint>

#define HD 128
#define TILE_M 128
#define NTH 256
#define MAXT 8
#define XSTR_H 264                    // X row stride in halves (528 B), conflict-free ldsm
#define XROW_B 528
#define WSTR_H 72                     // W chunk row stride in halves (144 B)
#define WROW_B 144
#define WCH_B (128 * WSTR_H * 2)      // 18432 B per chunk (128 n-rows x 64 k-halves + pad)
#define X_BYTES (TILE_M * XSTR_H * 2) // 67584
#define W_OFF X_BYTES
#define IDX_OFF (W_OFF + 2 * WCH_B)       // 104448
#define MB_OFF (IDX_OFF + 2 * TILE_M * 4) // 105472
#define SMEM_DYN (MB_OFF + 32)

// pre-transposed fp16 weights: [t][chunk][n=128][WSTR_H], 64 k per chunk
__device__ __align__(16) __half g_W1h[MAXT * 4 * 128 * WSTR_H];
__device__ __align__(16) __half g_W2h[MAXT * 2 * 128 * WSTR_H];

static __device__ __forceinline__ uint32_t h2u(__half2 h) {
    return *reinterpret_cast<uint32_t*>(&h);
}
static __device__ __forceinline__ uint32_t s2u(const void* p) {
    uint32_t a;
    asm("{ .reg .u64 t; cvta.to.shared.u64 t, %1; cvt.u32.u64 %0, t; }" : "=r"(a) : "l"(p));
    return a;
}
static __device__ __forceinline__ void mma16(float* c, const uint32_t* a, uint32_t b0, uint32_t b1) {
    asm volatile(
        "mma.sync.aligned.m16n8k16.row.col.f32.f16.f16.f32 "
        "{%0,%1,%2,%3}, {%4,%5,%6,%7}, {%8,%9}, {%0,%1,%2,%3};"
        : "+f"(c[0]), "+f"(c[1]), "+f"(c[2]), "+f"(c[3])
        : "r"(a[0]), "r"(a[1]), "r"(a[2]), "r"(a[3]), "r"(b0), "r"(b1));
}
static __device__ __forceinline__ void ldsm4(uint32_t* r, uint32_t addr) {
    asm volatile("ldmatrix.sync.aligned.m8n8.x4.shared.b16 {%0,%1,%2,%3}, [%4];"
                 : "=r"(r[0]), "=r"(r[1]), "=r"(r[2]), "=r"(r[3]) : "r"(addr));
}
static __device__ __forceinline__ void mbar_init(uint32_t m, uint32_t cnt) {
    asm volatile("mbarrier.init.shared.b64 [%0], %1;" :: "r"(m), "r"(cnt) : "memory");
}
static __device__ __forceinline__ void mbar_expect(uint32_t m, uint32_t bytes) {
    asm volatile("mbarrier.arrive.expect_tx.shared.b64 _, [%0], %1;" :: "r"(m), "r"(bytes) : "memory");
}
static __device__ __forceinline__ void mbar_arrive(uint32_t m) {
    asm volatile("mbarrier.arrive.shared.b64 _, [%0];" :: "r"(m) : "memory");
}
static __device__ __forceinline__ void mbar_wait(uint32_t m, uint32_t parity) {
    asm volatile(
        "{\n\t.reg .pred P;\n\tW_%=:\n\t"
        "mbarrier.try_wait.parity.shared.b64 P, [%0], %1;\n\t"
        "@!P bra W_%=;\n\t}"
        :: "r"(m), "r"(parity) : "memory");
}
static __device__ __forceinline__ void bulk_ld(uint32_t dst, const void* src, uint32_t bytes, uint32_t mbar) {
    asm volatile("cp.async.bulk.shared::cta.global.mbarrier::complete_tx::bytes [%0], [%1], %2, [%3];"
                 :: "r"(dst), "l"(src), "r"(bytes), "r"(mbar) : "memory");
}

// ---------------- prep: transpose + fp16-convert weights ----------------
__global__ void prep_w(const float* __restrict__ W1, const float* __restrict__ W2, int T) {
    int idx = blockIdx.x * blockDim.x + threadIdx.x;
    const int per_t1 = 4 * 128 * 64, per_t2 = 2 * 128 * 64;
    int tot1 = T * per_t1, tot2 = T * per_t2;
    if (idx < tot1) {
        int t = idx / per_t1, r = idx % per_t1;
        int c = r / (128 * 64), q = r % (128 * 64);
        int n = q / 64, kl = q % 64;
        float v = W1[(size_t)t * 256 * 128 + (size_t)(c * 64 + kl) * 128 + n];
        g_W1h[(((size_t)t * 4 + c) * 128 + n) * WSTR_H + kl] = __float2half_rn(v);
    } else if (idx < tot1 + tot2) {
        int j = idx - tot1;
        int t = j / per_t2, r = j % per_t2;
        int c = r / (128 * 64), q = r % (128 * 64);
        int n = q / 64, kl = q % 64;
        float v = W2[(size_t)t * 128 * 128 + (size_t)(c * 64 + kl) * 128 + n];
        g_W2h[(((size_t)t * 2 + c) * 128 + n) * WSTR_H + kl] = __float2half_rn(v);
    }
}

__global__ void zero_kernel(float4* __restrict__ out, int n4) {
    int i = blockIdx.x * blockDim.x + threadIdx.x;
    if (i < n4) out[i] = make_float4(0.f, 0.f, 0.f, 0.f);
}

// one 64-k chunk: 4 k16-steps; per step: 2 A ldsm.x4 + 4 B ldsm.x4 + 16 mma
static __device__ __forceinline__ void gemm_chunk(float acc[2][8][4], uint32_t xa, uint32_t wb) {
    #pragma unroll
    for (int ks = 0; ks < 4; ks++) {
        uint32_t a0[4], a1[4], b[4][4];
        ldsm4(a0, xa + ks * 32);
        ldsm4(a1, xa + 16 * XROW_B + ks * 32);
        #pragma unroll
        for (int p = 0; p < 4; p++) ldsm4(b[p], wb + p * (16 * WROW_B) + ks * 32);
        #pragma unroll
        for (int j = 0; j < 8; j++) {
            mma16(acc[0][j], a0, b[j >> 1][(j & 1) * 2], b[j >> 1][(j & 1) * 2 + 1]);
            mma16(acc[1][j], a1, b[j >> 1][(j & 1) * 2], b[j >> 1][(j & 1) * 2 + 1]);
        }
    }
}

__global__ void __launch_bounds__(NTH, 2)
relmp_mma(const float* __restrict__ ns, const int* __restrict__ adj,
          float* __restrict__ out, int E) {
    extern __shared__ char raw[];
    __half* Xh = (__half*)raw;
    float*  Xf = (float*)raw;
    uint32_t Su = s2u(raw);
    const uint32_t Xu = Su;
    const uint32_t Wu = Su + W_OFF;
    int* s_src = (int*)(raw + IDX_OFF);
    int* s_tgt = s_src + TILE_M;
    const uint32_t mbF[2] = { Su + MB_OFF, Su + MB_OFF + 8 };
    const uint32_t mbE[2] = { Su + MB_OFF + 16, Su + MB_OFF + 24 };

    const int tid = threadIdx.x, warp = tid >> 5, lane = tid & 31;
    const int gid = lane >> 2, tig = lane & 3;
    const int wm = warp & 3, wn = warp >> 2;
    const int t = blockIdx.y, e0 = blockIdx.x * TILE_M;
    const int m_valid = min(TILE_M, E - e0);

    if (tid == 0) {
        mbar_init(mbF[0], 1); mbar_init(mbF[1], 1);
        mbar_init(mbE[0], NTH); mbar_init(mbE[1], NTH);
    }
    if (tid < TILE_M) {
        int e = e0 + tid;
        int2 p = (e < E) ? ((const int2*)adj)[(size_t)t * E + e] : make_int2(0, 0);
        s_src[tid] = p.x; s_tgt[tid] = p.y;
    }
    __syncthreads();

    const __half* w1b = g_W1h + (size_t)t * 4 * 128 * WSTR_H;
    const __half* w2b = g_W2h + (size_t)t * 2 * 128 * WSTR_H;
    if (tid == 0) {
        mbar_expect(mbF[0], WCH_B); bulk_ld(Wu,         w1b,                WCH_B, mbF[0]);
        mbar_expect(mbF[1], WCH_B); bulk_ld(Wu + WCH_B, w1b + 128 * WSTR_H, WCH_B, mbF[1]);
    }

    // ---- gather: both halves, fp16, X[m][side*128 + k] ----
    for (int r = warp; r < 2 * TILE_M; r += 8) {
        int m = r >> 1, side = r & 1;
        int node = side ? s_tgt[m] : s_src[m];
        float4 v = ((const float4*)(ns + (size_t)node * HD))[lane];
        uint2 w;
        w.x = h2u(__floats2half2_rn(v.x, v.y));
        w.y = h2u(__floats2half2_rn(v.z, v.w));
        *(uint2*)(Xh + (size_t)m * XSTR_H + side * HD + lane * 4) = w;
    }
    __syncthreads();

    // per-lane ldsm base offsets (bytes)
    const uint32_t arow = (uint32_t)(wm * 32 + (lane & 15)) * XROW_B + ((lane >> 4) & 1) * 16;
    const uint32_t brow = (uint32_t)(wn * 64 + ((lane & 7) + ((lane & 16) >> 1))) * WROW_B + ((lane & 8) << 1);

    int pf[2] = {0, 0}, pe[2] = {0, 0};

#define CONSUME(cidx, ccolbytes, ACC) do {                                           \
        const int b_ = (cidx) & 1;                                                   \
        mbar_wait(mbF[b_], pf[b_]); pf[b_] ^= 1;                                     \
        gemm_chunk(ACC, Xu + arow + (ccolbytes), Wu + b_ * WCH_B + brow);            \
        mbar_arrive(mbE[b_]);                                                        \
        if (tid == 0 && (cidx) + 2 < 6) {                                            \
            mbar_wait(mbE[b_], pe[b_]); pe[b_] ^= 1;                                 \
            const __half* src_ = ((cidx) + 2 < 4) ? (w1b + ((cidx) + 2) * 128 * WSTR_H) \
                                                  : (w2b + ((cidx) - 2) * 128 * WSTR_H); \
            mbar_expect(mbF[b_], WCH_B);                                             \
            bulk_ld(Wu + b_ * WCH_B, src_, WCH_B, mbF[b_]);                          \
        }                                                                            \
    } while (0)

    float acc[2][8][4];
    #pragma unroll
    for (int i = 0; i < 2; i++)
        #pragma unroll
        for (int j = 0; j < 8; j++)
            #pragma unroll
            for (int q = 0; q < 4; q++) acc[i][j][q] = 0.f;

    // GEMM1: K=256, chunks 0..3
    #pragma unroll
    for (int c = 0; c < 4; c++) CONSUME(c, c * 128, acc);
    __syncthreads();

    // epilogue1: H = relu(acc) -> fp16 into X cols 0..127
    #pragma unroll
    for (int i = 0; i < 2; i++) {
        int r0 = wm * 32 + i * 16 + gid;
        #pragma unroll
        for (int j = 0; j < 8; j++) {
            int cn = wn * 64 + j * 8 + tig * 2;
            __half2 lo = __floats2half2_rn(fmaxf(acc[i][j][0], 0.f), fmaxf(acc[i][j][1], 0.f));
            __half2 hi = __floats2half2_rn(fmaxf(acc[i][j][2], 0.f), fmaxf(acc[i][j][3], 0.f));
            *(__half2*)(Xh + (size_t)r0 * XSTR_H + cn)       = lo;
            *(__half2*)(Xh + (size_t)(r0 + 8) * XSTR_H + cn) = hi;
        }
    }
    __syncthreads();

    // GEMM2: K=128, chunks 4..5
    float acc2[2][8][4];
    #pragma unroll
    for (int i = 0; i < 2; i++)
        #pragma unroll
        for (int j = 0; j < 8; j++)
            #pragma unroll
            for (int q = 0; q < 4; q++) acc2[i][j][q] = 0.f;

    #pragma unroll
    for (int c = 4; c < 6; c++) CONSUME(c, (c - 4) * 128, acc2);
    __syncthreads();

    // epilogue2: relu(MSG) fp32 -> X region (row stride 132 floats = 528 B)
    #pragma unroll
    for (int i = 0; i < 2; i++) {
        int r0 = wm * 32 + i * 16 + gid;
        #pragma unroll
        for (int j = 0; j < 8; j++) {
            int cn = wn * 64 + j * 8 + tig * 2;
            float2 lo, hi;
            lo.x = fmaxf(acc2[i][j][0], 0.f);
            lo.y = fmaxf(acc2[i][j][1], 0.f);
            hi.x = fmaxf(acc2[i][j][2], 0.f);
            hi.y = fmaxf(acc2[i][j][3], 0.f);
            *(float2*)(Xf + (size_t)r0 * 132 + cn)       = lo;
            *(float2*)(Xf + (size_t)(r0 + 8) * 132 + cn) = hi;
        }
    }
    __syncthreads();

    // scatter-add: warp per row, red.global.add.v4
    for (int m = warp; m < m_valid; m += 8) {
        int node = s_tgt[m];
        float4 v = *(const float4*)(Xf + (size_t)m * 132 + lane * 4);
        float* dst = out + (size_t)node * HD + lane * 4;
        asm volatile("red.global.add.v4.f32 [%0], {%1,%2,%3,%4};"
                     :: "l"(dst), "f"(v.x), "f"(v.y), "f"(v.z), "f"(v.w) : "memory");
    }
#undef CONSUME
}

extern "C" void kernel_launch(void* const* d_in, const int* in_sizes, int n_in,
                              void* d_out, int out_size) {
    const float* node_states = (const float*)d_in[0];
    const int*   adj         = (const int*)d_in[1];
    const float* W1          = (const float*)d_in[2];
    const float* W2          = (const float*)d_in[3];
    float*       out         = (float*)d_out;

    const int T = in_sizes[3] / (HD * HD);
    const int E = in_sizes[1] / (T * 2);

    int n4 = out_size / 4;
    zero_kernel<<<(n4 + 255) / 256, 256>>>((float4*)out, n4);

    int wtot = T * (4 + 2) * 128 * 64;
    prep_w<<<(wtot + 255) / 256, 256>>>(W1, W2, T);

    const int tiles = (E + TILE_M - 1) / TILE_M;
    cudaFuncSetAttribute(relmp_mma, cudaFuncAttributeMaxDynamicSharedMemorySize, SMEM_DYN);
    relmp_mma<<<dim3(tiles, T), NTH, SMEM_DYN>>>(node_states, adj, out, E);
}

// round 8
// speedup vs baseline: 2.9556x; 1.0848x over previous
#include <cuda_runtime.h>
#include <cuda_fp16.h>
#include <cstdint>

#define HD 128
#define TILE_M 128
#define NTH 256
#define MAXT 8
#define MAXN 100000
#define XSTR_H 264                    // X row stride in halves (528 B), conflict-free ldsm
#define XROW_B 528
#define WSTR_H 72                     // W chunk row stride in halves (144 B)
#define WROW_B 144
#define WCH_B (128 * WSTR_H * 2)      // 18432 B per chunk (128 n-rows x 64 k-halves + pad)
#define X_BYTES (TILE_M * XSTR_H * 2) // 67584
#define W_OFF X_BYTES
#define IDX_OFF (W_OFF + 2 * WCH_B)       // 104448
#define MB_OFF (IDX_OFF + 2 * TILE_M * 4) // 105472
#define SMEM_DYN (MB_OFF + 32)

// pre-transposed fp16 weights: [t][chunk][n=128][WSTR_H], 64 k per chunk
__device__ __align__(16) __half g_W1h[MAXT * 4 * 128 * WSTR_H];
__device__ __align__(16) __half g_W2h[MAXT * 2 * 128 * WSTR_H];
// fp16 copy of node_states (L2-resident working set: 25.6 MB)
__device__ __align__(16) __half g_ns16[(size_t)MAXN * HD];

static __device__ __forceinline__ uint32_t h2u(__half2 h) {
    return *reinterpret_cast<uint32_t*>(&h);
}
static __device__ __forceinline__ uint32_t s2u(const void* p) {
    uint32_t a;
    asm("{ .reg .u64 t; cvta.to.shared.u64 t, %1; cvt.u32.u64 %0, t; }" : "=r"(a) : "l"(p));
    return a;
}
static __device__ __forceinline__ void mma16(float* c, const uint32_t* a, uint32_t b0, uint32_t b1) {
    asm volatile(
        "mma.sync.aligned.m16n8k16.row.col.f32.f16.f16.f32 "
        "{%0,%1,%2,%3}, {%4,%5,%6,%7}, {%8,%9}, {%0,%1,%2,%3};"
        : "+f"(c[0]), "+f"(c[1]), "+f"(c[2]), "+f"(c[3])
        : "r"(a[0]), "r"(a[1]), "r"(a[2]), "r"(a[3]), "r"(b0), "r"(b1));
}
static __device__ __forceinline__ void ldsm4(uint32_t* r, uint32_t addr) {
    asm volatile("ldmatrix.sync.aligned.m8n8.x4.shared.b16 {%0,%1,%2,%3}, [%4];"
                 : "=r"(r[0]), "=r"(r[1]), "=r"(r[2]), "=r"(r[3]) : "r"(addr));
}
static __device__ __forceinline__ void mbar_init(uint32_t m, uint32_t cnt) {
    asm volatile("mbarrier.init.shared.b64 [%0], %1;" :: "r"(m), "r"(cnt) : "memory");
}
static __device__ __forceinline__ void mbar_expect(uint32_t m, uint32_t bytes) {
    asm volatile("mbarrier.arrive.expect_tx.shared.b64 _, [%0], %1;" :: "r"(m), "r"(bytes) : "memory");
}
static __device__ __forceinline__ void mbar_arrive(uint32_t m) {
    asm volatile("mbarrier.arrive.shared.b64 _, [%0];" :: "r"(m) : "memory");
}
static __device__ __forceinline__ void mbar_wait(uint32_t m, uint32_t parity) {
    asm volatile(
        "{\n\t.reg .pred P;\n\tW_%=:\n\t"
        "mbarrier.try_wait.parity.shared.b64 P, [%0], %1;\n\t"
        "@!P bra W_%=;\n\t}"
        :: "r"(m), "r"(parity) : "memory");
}
static __device__ __forceinline__ void bulk_ld(uint32_t dst, const void* src, uint32_t bytes, uint32_t mbar) {
    asm volatile("cp.async.bulk.shared::cta.global.mbarrier::complete_tx::bytes [%0], [%1], %2, [%3];"
                 :: "r"(dst), "l"(src), "r"(bytes), "r"(mbar) : "memory");
}

// ---------------- prep: zero output + fp16 node_states + transposed fp16 weights ----------------
__global__ void prep_all(const float* __restrict__ ns, const float* __restrict__ W1,
                         const float* __restrict__ W2, float4* __restrict__ out,
                         int N, int T, int n4) {
    int idx = blockIdx.x * blockDim.x + threadIdx.x;
    int stride = gridDim.x * blockDim.x;

    // zero output
    for (int i = idx; i < n4; i += stride) out[i] = make_float4(0.f, 0.f, 0.f, 0.f);

    // node_states -> fp16 (one float4 -> two half2 per thread-item)
    int nns = N * (HD / 4);
    for (int i = idx; i < nns; i += stride) {
        float4 v = ((const float4*)ns)[i];
        uint2 w;
        __half2 a = __floats2half2_rn(v.x, v.y);
        __half2 b = __floats2half2_rn(v.z, v.w);
        w.x = *reinterpret_cast<uint32_t*>(&a);
        w.y = *reinterpret_cast<uint32_t*>(&b);
        *(uint2*)(g_ns16 + (size_t)i * 4) = w;
    }

    // weights: transpose + fp16
    const int per_t1 = 4 * 128 * 64, per_t2 = 2 * 128 * 64;
    int tot1 = T * per_t1, tot2 = T * per_t2;
    for (int i = idx; i < tot1 + tot2; i += stride) {
        if (i < tot1) {
            int t = i / per_t1, r = i % per_t1;
            int c = r / (128 * 64), q = r % (128 * 64);
            int n = q / 64, kl = q % 64;
            float v = W1[(size_t)t * 256 * 128 + (size_t)(c * 64 + kl) * 128 + n];
            g_W1h[(((size_t)t * 4 + c) * 128 + n) * WSTR_H + kl] = __float2half_rn(v);
        } else {
            int j = i - tot1;
            int t = j / per_t2, r = j % per_t2;
            int c = r / (128 * 64), q = r % (128 * 64);
            int n = q / 64, kl = q % 64;
            float v = W2[(size_t)t * 128 * 128 + (size_t)(c * 64 + kl) * 128 + n];
            g_W2h[(((size_t)t * 2 + c) * 128 + n) * WSTR_H + kl] = __float2half_rn(v);
        }
    }
}

// one 64-k chunk: 4 k16-steps; per step: 2 A ldsm.x4 + 4 B ldsm.x4 + 16 mma
static __device__ __forceinline__ void gemm_chunk(float acc[2][8][4], uint32_t xa, uint32_t wb) {
    #pragma unroll
    for (int ks = 0; ks < 4; ks++) {
        uint32_t a0[4], a1[4], b[4][4];
        ldsm4(a0, xa + ks * 32);
        ldsm4(a1, xa + 16 * XROW_B + ks * 32);
        #pragma unroll
        for (int p = 0; p < 4; p++) ldsm4(b[p], wb + p * (16 * WROW_B) + ks * 32);
        #pragma unroll
        for (int j = 0; j < 8; j++) {
            mma16(acc[0][j], a0, b[j >> 1][(j & 1) * 2], b[j >> 1][(j & 1) * 2 + 1]);
            mma16(acc[1][j], a1, b[j >> 1][(j & 1) * 2], b[j >> 1][(j & 1) * 2 + 1]);
        }
    }
}

__global__ void __launch_bounds__(NTH, 2)
relmp_mma(const int* __restrict__ adj, float* __restrict__ out, int E) {
    extern __shared__ char raw[];
    __half* Xh = (__half*)raw;
    float*  Xf = (float*)raw;
    uint32_t Su = s2u(raw);
    const uint32_t Xu = Su;
    const uint32_t Wu = Su + W_OFF;
    int* s_src = (int*)(raw + IDX_OFF);
    int* s_tgt = s_src + TILE_M;
    const uint32_t mbF[2] = { Su + MB_OFF, Su + MB_OFF + 8 };
    const uint32_t mbE[2] = { Su + MB_OFF + 16, Su + MB_OFF + 24 };

    const int tid = threadIdx.x, warp = tid >> 5, lane = tid & 31;
    const int gid = lane >> 2, tig = lane & 3;
    const int wm = warp & 3, wn = warp >> 2;
    const int t = blockIdx.y, e0 = blockIdx.x * TILE_M;
    const int m_valid = min(TILE_M, E - e0);

    if (tid == 0) {
        mbar_init(mbF[0], 1); mbar_init(mbF[1], 1);
        mbar_init(mbE[0], 8); mbar_init(mbE[1], 8);   // one arrive per warp
    }
    if (tid < TILE_M) {
        int e = e0 + tid;
        int2 p = (e < E) ? ((const int2*)adj)[(size_t)t * E + e] : make_int2(0, 0);
        s_src[tid] = p.x; s_tgt[tid] = p.y;
    }
    __syncthreads();

    const __half* w1b = g_W1h + (size_t)t * 4 * 128 * WSTR_H;
    const __half* w2b = g_W2h + (size_t)t * 2 * 128 * WSTR_H;
    if (tid == 0) {
        mbar_expect(mbF[0], WCH_B); bulk_ld(Wu,         w1b,                WCH_B, mbF[0]);
        mbar_expect(mbF[1], WCH_B); bulk_ld(Wu + WCH_B, w1b + 128 * WSTR_H, WCH_B, mbF[1]);
    }

    // ---- gather: both halves from fp16 table, X[m][side*128 + k] ----
    for (int r = warp; r < 2 * TILE_M; r += 8) {
        int m = r >> 1, side = r & 1;
        int node = side ? s_tgt[m] : s_src[m];
        uint2 v = ((const uint2*)(g_ns16 + (size_t)node * HD))[lane];
        *(uint2*)(Xh + (size_t)m * XSTR_H + side * HD + lane * 4) = v;
    }
    __syncthreads();

    // per-lane ldsm base offsets (bytes)
    const uint32_t arow = (uint32_t)(wm * 32 + (lane & 15)) * XROW_B + ((lane >> 4) & 1) * 16;
    const uint32_t brow = (uint32_t)(wn * 64 + ((lane & 7) + ((lane & 16) >> 1))) * WROW_B + ((lane & 8) << 1);

    int pf[2] = {0, 0}, pe[2] = {0, 0};

#define CONSUME(cidx, ccolbytes, ACC) do {                                           \
        const int b_ = (cidx) & 1;                                                   \
        mbar_wait(mbF[b_], pf[b_]); pf[b_] ^= 1;                                     \
        gemm_chunk(ACC, Xu + arow + (ccolbytes), Wu + b_ * WCH_B + brow);            \
        if (lane == 0) mbar_arrive(mbE[b_]);                                         \
        if (tid == 0 && (cidx) + 2 < 6) {                                            \
            mbar_wait(mbE[b_], pe[b_]); pe[b_] ^= 1;                                 \
            const __half* src_ = ((cidx) + 2 < 4) ? (w1b + ((cidx) + 2) * 128 * WSTR_H) \
                                                  : (w2b + ((cidx) - 2) * 128 * WSTR_H); \
            mbar_expect(mbF[b_], WCH_B);                                             \
            bulk_ld(Wu + b_ * WCH_B, src_, WCH_B, mbF[b_]);                          \
        }                                                                            \
    } while (0)

    float acc[2][8][4];
    #pragma unroll
    for (int i = 0; i < 2; i++)
        #pragma unroll
        for (int j = 0; j < 8; j++)
            #pragma unroll
            for (int q = 0; q < 4; q++) acc[i][j][q] = 0.f;

    // GEMM1: K=256, chunks 0..3
    #pragma unroll
    for (int c = 0; c < 4; c++) CONSUME(c, c * 128, acc);
    __syncthreads();

    // epilogue1: H = relu(acc) -> fp16 into X cols 0..127
    #pragma unroll
    for (int i = 0; i < 2; i++) {
        int r0 = wm * 32 + i * 16 + gid;
        #pragma unroll
        for (int j = 0; j < 8; j++) {
            int cn = wn * 64 + j * 8 + tig * 2;
            __half2 lo = __floats2half2_rn(fmaxf(acc[i][j][0], 0.f), fmaxf(acc[i][j][1], 0.f));
            __half2 hi = __floats2half2_rn(fmaxf(acc[i][j][2], 0.f), fmaxf(acc[i][j][3], 0.f));
            *(__half2*)(Xh + (size_t)r0 * XSTR_H + cn)       = lo;
            *(__half2*)(Xh + (size_t)(r0 + 8) * XSTR_H + cn) = hi;
        }
    }
    __syncthreads();

    // GEMM2: K=128, chunks 4..5
    float acc2[2][8][4];
    #pragma unroll
    for (int i = 0; i < 2; i++)
        #pragma unroll
        for (int j = 0; j < 8; j++)
            #pragma unroll
            for (int q = 0; q < 4; q++) acc2[i][j][q] = 0.f;

    #pragma unroll
    for (int c = 4; c < 6; c++) CONSUME(c, (c - 4) * 128, acc2);
    __syncthreads();

    // epilogue2: relu(MSG) fp32 -> X region (row stride 132 floats = 528 B)
    #pragma unroll
    for (int i = 0; i < 2; i++) {
        int r0 = wm * 32 + i * 16 + gid;
        #pragma unroll
        for (int j = 0; j < 8; j++) {
            int cn = wn * 64 + j * 8 + tig * 2;
            float2 lo, hi;
            lo.x = fmaxf(acc2[i][j][0], 0.f);
            lo.y = fmaxf(acc2[i][j][1], 0.f);
            hi.x = fmaxf(acc2[i][j][2], 0.f);
            hi.y = fmaxf(acc2[i][j][3], 0.f);
            *(float2*)(Xf + (size_t)r0 * 132 + cn)       = lo;
            *(float2*)(Xf + (size_t)(r0 + 8) * 132 + cn) = hi;
        }
    }
    __syncthreads();

    // scatter-add: warp per row, red.global.add.v4
    for (int m = warp; m < m_valid; m += 8) {
        int node = s_tgt[m];
        float4 v = *(const float4*)(Xf + (size_t)m * 132 + lane * 4);
        float* dst = out + (size_t)node * HD + lane * 4;
        asm volatile("red.global.add.v4.f32 [%0], {%1,%2,%3,%4};"
                     :: "l"(dst), "f"(v.x), "f"(v.y), "f"(v.z), "f"(v.w) : "memory");
    }
#undef CONSUME
}

extern "C" void kernel_launch(void* const* d_in, const int* in_sizes, int n_in,
                              void* d_out, int out_size) {
    const float* node_states = (const float*)d_in[0];
    const int*   adj         = (const int*)d_in[1];
    const float* W1          = (const float*)d_in[2];
    const float* W2          = (const float*)d_in[3];
    float*       out         = (float*)d_out;

    const int T = in_sizes[3] / (HD * HD);
    const int E = in_sizes[1] / (T * 2);
    const int N = in_sizes[0] / HD;

    int n4 = out_size / 4;
    int work = n4;
    int nns = N * (HD / 4);
    if (nns > work) work = nns;
    prep_all<<<(work + 255) / 256, 256>>>(node_states, W1, W2, (float4*)out, N, T, n4);

    const int tiles = (E + TILE_M - 1) / TILE_M;
    cudaFuncSetAttribute(relmp_mma, cudaFuncAttributeMaxDynamicSharedMemorySize, SMEM_DYN);
    relmp_mma<<<dim3(tiles, T), NTH, SMEM_DYN>>>(adj, out, E);
}

// round 9
// speedup vs baseline: 3.3938x; 1.1482x over previous
#include <cuda_runtime.h>
#include <cuda_fp16.h>
#include <cstdint>

#define HD 128
#define TILE_M 128
#define NTH 256
#define MAXT 8
#define MAXN 100000
#define XSTR_H 264                    // X row stride in halves (528 B), conflict-free ldsm
#define XROW_B 528
#define WSTR_H 72                     // W chunk row stride in halves (144 B)
#define WROW_B 144
#define WCH_B (128 * WSTR_H * 2)      // 18432 B per chunk
#define X_BYTES (TILE_M * XSTR_H * 2) // 67584
#define W_OFF X_BYTES
#define IDX_OFF (W_OFF + 2 * WCH_B)       // 104448
#define MB_OFF (IDX_OFF + 2 * TILE_M * 4) // 105472
#define SMEM_DYN (MB_OFF + 32)

// pre-transposed fp16 weights: [t][chunk][n=128][WSTR_H], 64 k per chunk
__device__ __align__(16) __half g_W1h[MAXT * 4 * 128 * WSTR_H];
__device__ __align__(16) __half g_W2h[MAXT * 2 * 128 * WSTR_H];
// fp16 copy of node_states (25.6 MB, L2-resident)
__device__ __align__(16) __half g_ns16[(size_t)MAXN * HD];

static __device__ __forceinline__ uint32_t s2u(const void* p) {
    uint32_t a;
    asm("{ .reg .u64 t; cvta.to.shared.u64 t, %1; cvt.u32.u64 %0, t; }" : "=r"(a) : "l"(p));
    return a;
}
static __device__ __forceinline__ void mma16(float* c, const uint32_t* a, uint32_t b0, uint32_t b1) {
    asm volatile(
        "mma.sync.aligned.m16n8k16.row.col.f32.f16.f16.f32 "
        "{%0,%1,%2,%3}, {%4,%5,%6,%7}, {%8,%9}, {%0,%1,%2,%3};"
        : "+f"(c[0]), "+f"(c[1]), "+f"(c[2]), "+f"(c[3])
        : "r"(a[0]), "r"(a[1]), "r"(a[2]), "r"(a[3]), "r"(b0), "r"(b1));
}
static __device__ __forceinline__ void ldsm4(uint32_t* r, uint32_t addr) {
    asm volatile("ldmatrix.sync.aligned.m8n8.x4.shared.b16 {%0,%1,%2,%3}, [%4];"
                 : "=r"(r[0]), "=r"(r[1]), "=r"(r[2]), "=r"(r[3]) : "r"(addr));
}
static __device__ __forceinline__ void mbar_init(uint32_t m, uint32_t cnt) {
    asm volatile("mbarrier.init.shared.b64 [%0], %1;" :: "r"(m), "r"(cnt) : "memory");
}
static __device__ __forceinline__ void mbar_expect(uint32_t m, uint32_t bytes) {
    asm volatile("mbarrier.arrive.expect_tx.shared.b64 _, [%0], %1;" :: "r"(m), "r"(bytes) : "memory");
}
static __device__ __forceinline__ void mbar_arrive(uint32_t m) {
    asm volatile("mbarrier.arrive.shared.b64 _, [%0];" :: "r"(m) : "memory");
}
static __device__ __forceinline__ void mbar_wait(uint32_t m, uint32_t parity) {
    asm volatile(
        "{\n\t.reg .pred P;\n\tW_%=:\n\t"
        "mbarrier.try_wait.parity.shared.b64 P, [%0], %1;\n\t"
        "@!P bra W_%=;\n\t}"
        :: "r"(m), "r"(parity) : "memory");
}
static __device__ __forceinline__ void bulk_ld(uint32_t dst, const void* src, uint32_t bytes, uint32_t mbar) {
    asm volatile("cp.async.bulk.shared::cta.global.mbarrier::complete_tx::bytes [%0], [%1], %2, [%3];"
                 :: "r"(dst), "l"(src), "r"(bytes), "r"(mbar) : "memory");
}
static __device__ __forceinline__ void red2(float* dst, float a, float b) {
    asm volatile("red.global.add.v2.f32 [%0], {%1,%2};" :: "l"(dst), "f"(a), "f"(b) : "memory");
}

// ---------------- prep: zero output + fp16 node_states + transposed fp16 weights ----------------
__global__ void prep_all(const float* __restrict__ ns, const float* __restrict__ W1,
                         const float* __restrict__ W2, float4* __restrict__ out,
                         int N, int T, int n4) {
    int idx = blockIdx.x * blockDim.x + threadIdx.x;
    int stride = gridDim.x * blockDim.x;

    for (int i = idx; i < n4; i += stride) out[i] = make_float4(0.f, 0.f, 0.f, 0.f);

    int nns = N * (HD / 4);
    for (int i = idx; i < nns; i += stride) {
        float4 v = ((const float4*)ns)[i];
        uint2 w;
        __half2 a = __floats2half2_rn(v.x, v.y);
        __half2 b = __floats2half2_rn(v.z, v.w);
        w.x = *reinterpret_cast<uint32_t*>(&a);
        w.y = *reinterpret_cast<uint32_t*>(&b);
        *(uint2*)(g_ns16 + (size_t)i * 4) = w;
    }

    const int per_t1 = 4 * 128 * 64, per_t2 = 2 * 128 * 64;
    int tot1 = T * per_t1, tot2 = T * per_t2;
    for (int i = idx; i < tot1 + tot2; i += stride) {
        if (i < tot1) {
            int t = i / per_t1, r = i % per_t1;
            int c = r / (128 * 64), q = r % (128 * 64);
            int n = q / 64, kl = q % 64;
            float v = W1[(size_t)t * 256 * 128 + (size_t)(c * 64 + kl) * 128 + n];
            g_W1h[(((size_t)t * 4 + c) * 128 + n) * WSTR_H + kl] = __float2half_rn(v);
        } else {
            int j = i - tot1;
            int t = j / per_t2, r = j % per_t2;
            int c = r / (128 * 64), q = r % (128 * 64);
            int n = q / 64, kl = q % 64;
            float v = W2[(size_t)t * 128 * 128 + (size_t)(c * 64 + kl) * 128 + n];
            g_W2h[(((size_t)t * 2 + c) * 128 + n) * WSTR_H + kl] = __float2half_rn(v);
        }
    }
}

// one 64-k chunk: 4 k16-steps; per step: 2 A ldsm.x4 + 4 B ldsm.x4 + 16 mma
static __device__ __forceinline__ void gemm_chunk(float acc[2][8][4], uint32_t xa, uint32_t wb) {
    #pragma unroll
    for (int ks = 0; ks < 4; ks++) {
        uint32_t a0[4], a1[4], b[4][4];
        ldsm4(a0, xa + ks * 32);
        ldsm4(a1, xa + 16 * XROW_B + ks * 32);
        #pragma unroll
        for (int p = 0; p < 4; p++) ldsm4(b[p], wb + p * (16 * WROW_B) + ks * 32);
        #pragma unroll
        for (int j = 0; j < 8; j++) {
            mma16(acc[0][j], a0, b[j >> 1][(j & 1) * 2], b[j >> 1][(j & 1) * 2 + 1]);
            mma16(acc[1][j], a1, b[j >> 1][(j & 1) * 2], b[j >> 1][(j & 1) * 2 + 1]);
        }
    }
}

__global__ void __launch_bounds__(NTH, 2)
relmp_mma(const int* __restrict__ adj, float* __restrict__ out, int E) {
    extern __shared__ char raw[];
    __half* Xh = (__half*)raw;
    uint32_t Su = s2u(raw);
    const uint32_t Xu = Su;
    const uint32_t Wu = Su + W_OFF;
    int* s_src = (int*)(raw + IDX_OFF);
    int* s_tgt = s_src + TILE_M;
    const uint32_t mbF[2] = { Su + MB_OFF, Su + MB_OFF + 8 };
    const uint32_t mbE[2] = { Su + MB_OFF + 16, Su + MB_OFF + 24 };

    const int tid = threadIdx.x, warp = tid >> 5, lane = tid & 31;
    const int gid = lane >> 2, tig = lane & 3;
    const int wm = warp & 3, wn = warp >> 2;
    const int t = blockIdx.y, e0 = blockIdx.x * TILE_M;
    const int m_valid = min(TILE_M, E - e0);

    if (tid == 0) {
        mbar_init(mbF[0], 1); mbar_init(mbF[1], 1);
        mbar_init(mbE[0], 8); mbar_init(mbE[1], 8);   // one arrive per warp
    }
    if (tid < TILE_M) {
        int e = e0 + tid;
        int2 p = (e < E) ? ((const int2*)adj)[(size_t)t * E + e] : make_int2(0, 0);
        s_src[tid] = p.x; s_tgt[tid] = p.y;
    }
    __syncthreads();

    const __half* w1b = g_W1h + (size_t)t * 4 * 128 * WSTR_H;
    const __half* w2b = g_W2h + (size_t)t * 2 * 128 * WSTR_H;
    if (tid == 0) {
        mbar_expect(mbF[0], WCH_B); bulk_ld(Wu,         w1b,                WCH_B, mbF[0]);
        mbar_expect(mbF[1], WCH_B); bulk_ld(Wu + WCH_B, w1b + 128 * WSTR_H, WCH_B, mbF[1]);
    }

    // ---- gather: uint4 per lane, 2 rows per warp-iteration ----
    {
        const int hl = lane >> 4;        // half-warp id (row within pair)
        const int l16 = lane & 15;
        for (int rr = warp * 2; rr < 2 * TILE_M; rr += 16) {
            int r = rr + hl;
            int m = r >> 1, side = r & 1;
            int node = side ? s_tgt[m] : s_src[m];
            uint4 v = ((const uint4*)(g_ns16 + (size_t)node * HD))[l16];
            *(uint4*)(Xh + (size_t)m * XSTR_H + side * HD + l16 * 8) = v;
        }
    }
    __syncthreads();

    // per-lane ldsm base offsets (bytes)
    const uint32_t arow = (uint32_t)(wm * 32 + (lane & 15)) * XROW_B + ((lane >> 4) & 1) * 16;
    const uint32_t brow = (uint32_t)(wn * 64 + ((lane & 7) + ((lane & 16) >> 1))) * WROW_B + ((lane & 8) << 1);

    int pf[2] = {0, 0}, pe[2] = {0, 0};

#define CONSUME(cidx, ccolbytes, ACC) do {                                           \
        const int b_ = (cidx) & 1;                                                   \
        mbar_wait(mbF[b_], pf[b_]); pf[b_] ^= 1;                                     \
        gemm_chunk(ACC, Xu + arow + (ccolbytes), Wu + b_ * WCH_B + brow);            \
        if (lane == 0) mbar_arrive(mbE[b_]);                                         \
        if (tid == 0 && (cidx) + 2 < 6) {                                            \
            mbar_wait(mbE[b_], pe[b_]); pe[b_] ^= 1;                                 \
            const __half* src_ = ((cidx) + 2 < 4) ? (w1b + ((cidx) + 2) * 128 * WSTR_H) \
                                                  : (w2b + ((cidx) - 2) * 128 * WSTR_H); \
            mbar_expect(mbF[b_], WCH_B);                                             \
            bulk_ld(Wu + b_ * WCH_B, src_, WCH_B, mbF[b_]);                          \
        }                                                                            \
    } while (0)

    float acc[2][8][4];
    #pragma unroll
    for (int i = 0; i < 2; i++)
        #pragma unroll
        for (int j = 0; j < 8; j++)
            #pragma unroll
            for (int q = 0; q < 4; q++) acc[i][j][q] = 0.f;

    // GEMM1: K=256, chunks 0..3
    #pragma unroll
    for (int c = 0; c < 4; c++) CONSUME(c, c * 128, acc);
    __syncthreads();

    // epilogue1: H = relu(acc) -> fp16 into X cols 0..127
    #pragma unroll
    for (int i = 0; i < 2; i++) {
        int r0 = wm * 32 + i * 16 + gid;
        #pragma unroll
        for (int j = 0; j < 8; j++) {
            int cn = wn * 64 + j * 8 + tig * 2;
            __half2 lo = __floats2half2_rn(fmaxf(acc[i][j][0], 0.f), fmaxf(acc[i][j][1], 0.f));
            __half2 hi = __floats2half2_rn(fmaxf(acc[i][j][2], 0.f), fmaxf(acc[i][j][3], 0.f));
            *(__half2*)(Xh + (size_t)r0 * XSTR_H + cn)       = lo;
            *(__half2*)(Xh + (size_t)(r0 + 8) * XSTR_H + cn) = hi;
        }
    }
    __syncthreads();

    // GEMM2: K=128, chunks 4..5 (reuse acc registers)
    float acc2[2][8][4];
    #pragma unroll
    for (int i = 0; i < 2; i++)
        #pragma unroll
        for (int j = 0; j < 8; j++)
            #pragma unroll
            for (int q = 0; q < 4; q++) acc2[i][j][q] = 0.f;

    #pragma unroll
    for (int c = 4; c < 6; c++) CONSUME(c, (c - 4) * 128, acc2);

    // fused epilogue2 + scatter: relu + red.global.add.v2 straight from registers
    #pragma unroll
    for (int i = 0; i < 2; i++) {
        int r0 = wm * 32 + i * 16 + gid;
        int r1 = r0 + 8;
        int n0 = s_tgt[r0], n1 = s_tgt[r1];
        float* d0 = out + (size_t)n0 * HD + wn * 64 + tig * 2;
        float* d1 = out + (size_t)n1 * HD + wn * 64 + tig * 2;
        bool v0 = (r0 < m_valid), v1 = (r1 < m_valid);
        #pragma unroll
        for (int j = 0; j < 8; j++) {
            if (v0) red2(d0 + j * 8, fmaxf(acc2[i][j][0], 0.f), fmaxf(acc2[i][j][1], 0.f));
            if (v1) red2(d1 + j * 8, fmaxf(acc2[i][j][2], 0.f), fmaxf(acc2[i][j][3], 0.f));
        }
    }
#undef CONSUME
}

extern "C" void kernel_launch(void* const* d_in, const int* in_sizes, int n_in,
                              void* d_out, int out_size) {
    const float* node_states = (const float*)d_in[0];
    const int*   adj         = (const int*)d_in[1];
    const float* W1          = (const float*)d_in[2];
    const float* W2          = (const float*)d_in[3];
    float*       out         = (float*)d_out;

    const int T = in_sizes[3] / (HD * HD);
    const int E = in_sizes[1] / (T * 2);
    const int N = in_sizes[0] / HD;

    int n4 = out_size / 4;
    int work = n4;
    int nns = N * (HD / 4);
    if (nns > work) work = nns;
    prep_all<<<(work + 255) / 256, 256>>>(node_states, W1, W2, (float4*)out, N, T, n4);

    const int tiles = (E + TILE_M - 1) / TILE_M;
    cudaFuncSetAttribute(relmp_mma, cudaFuncAttributeMaxDynamicSharedMemorySize, SMEM_DYN);
    relmp_mma<<<dim3(tiles, T), NTH, SMEM_DYN>>>(adj, out, E);
}